// round 17
// baseline (speedup 1.0000x reference)
#include <cuda_runtime.h>
#include <math.h>
#include <cstdint>

// ---------------- problem constants ----------------
#define BB       256
#define DMODEL   2048
#define DINNER   8192
#define DSTATE   16
#define DTRANK   128
#define XPN      (DTRANK + 2*DSTATE)   // 160
#define SPLIT6   8
#define SPLIT3   32

// ---------------- scratch (device globals; no allocation) ----------------
__device__ float g_xz  [BB * 2 * DINNER];     // xi | z (plain)
__device__ float g_xc  [BB * DINNER];         // xc, tf32-rounded, k-permuted
__device__ float g_xdb [BB * XPN];            // x_db plain (Bm/Cm for ssm)
__device__ float g_dtin[BB * DTRANK];         // x_db[:, :128] tf32, permuted
__device__ float g_dt  [BB * DINNER];         // softplus(dt) plain
__device__ float g_A   [DINNER * DSTATE];
__device__ float g_xt  [BB * DMODEL];         // x tf32, permuted
__device__ float g_y   [BB * DINNER];         // y tf32, permuted
__device__ float g_part [SPLIT6 * BB * DMODEL];  // GEMM6 partials
__device__ float g_part3[SPLIT3 * BB * XPN];     // GEMM3 partials
__device__ int   g_cnt6 [64];                    // GEMM6 tile counters (zero-init)

// ---------------- helpers ----------------
__device__ __forceinline__ uint32_t smem_u32(const void* p) {
    uint32_t a;
    asm("{ .reg .u64 t; cvta.to.shared.u64 t, %1; cvt.u32.u64 %0, t; }" : "=r"(a) : "l"(p));
    return a;
}

__device__ __forceinline__ uint32_t f2tf32(float f) {
    uint32_t r;
    asm("cvt.rna.tf32.f32 %0, %1;" : "=r"(r) : "f"(f));
    return r;
}

__device__ __forceinline__ void mma_tf32(float* d, const uint32_t* a,
                                         uint32_t b0, uint32_t b1) {
    asm volatile(
        "mma.sync.aligned.m16n8k8.row.col.f32.tf32.tf32.f32 "
        "{%0,%1,%2,%3}, {%4,%5,%6,%7}, {%8,%9}, {%0,%1,%2,%3};"
        : "+f"(d[0]), "+f"(d[1]), "+f"(d[2]), "+f"(d[3])
        : "r"(a[0]), "r"(a[1]), "r"(a[2]), "r"(a[3]), "r"(b0), "r"(b1));
}

__device__ __forceinline__ void cp16(uint32_t s, const void* g) {
    asm volatile("cp.async.cg.shared.global [%0], [%1], 16;" :: "r"(s), "l"(g));
}
#define CP_COMMIT() asm volatile("cp.async.commit_group;" ::: "memory")
#define CP_WAIT(n)  asm volatile("cp.async.wait_group %0;" :: "n"(n) : "memory")

// k-permutation within each 8-group: storage order (0,4,1,5,2,6,3,7)
__device__ __forceinline__ int kperm(int j) { return ((j & 3) << 1) | (j >> 2); }

// ---------------- TF32 single-product GEMM ----------------
// C[M,N] (+)= A[M,K] * B[N,K]^T.
// A: tf32-rounded fp32, K-PERMUTED per 8-group (LDS.64 fragment pairs).
// B: raw fp32, cvt.rna at fragment load.
// 256 threads, tile 128x128x32, 3-stage cp.async (96 KB, 2 CTAs/SM),
// single __syncthreads per iter. smem chunk swizzle c^(r&7).
// EPI: 0 = store; 2 = store partials at C + z*partStride;
//      3 = softplus(acc + bias); 4 = partials + last-CTA fused reduction
//      into Cfinal (threadfence-reduction, self-resetting counters).
#define GBM 128
#define GBN 128
#define GBK 32
#define A_OFF 0
#define B_OFF 16384
#define STG_BYTES 32768
#define NSTAGE 3

template<int EPI, int SPLITK>
__global__ void __launch_bounds__(256, 2)
tf32_gemm(const float* __restrict__ Af, int lda,
          const float* __restrict__ Bf, int ldb,
          float* __restrict__ C, int ldc, int K, int nlim,
          size_t partStride, const float* __restrict__ bias,
          float* __restrict__ Cfinal, int* __restrict__ cnt)
{
    extern __shared__ char smraw[];

    const int tid = threadIdx.x;
    const int n0  = blockIdx.x * GBN;
    const int m0  = blockIdx.y * GBM;
    const int kChunk = K / SPLITK;
    const int kb  = blockIdx.z * kChunk;
    const int iters = kChunk / GBK;

    const uint32_t usm = smem_u32(smraw);

    auto issue = [&](uint32_t sbase, int koff) {
        #pragma unroll
        for (int u = 0; u < 4; u++) {
            int idx = u * 256 + tid;
            int r   = idx >> 3;
            int c   = idx & 7;
            uint32_t so = (uint32_t)(r * 128 + ((c ^ (r & 7)) * 16));
            cp16(sbase + A_OFF + so, Af + (size_t)(m0 + r) * lda + koff + c * 4);
            int rB = n0 + r; if (rB >= nlim) rB = nlim - 1;
            cp16(sbase + B_OFF + so, Bf + (size_t)rB * ldb + koff + c * 4);
        }
    };

    issue(usm, kb);                   CP_COMMIT();
    issue(usm + STG_BYTES, kb + GBK); CP_COMMIT();

    const int w    = tid >> 5;
    const int lane = tid & 31;
    const int wm   = (w & 1) * 64;
    const int wn   = (w >> 1) * 32;
    const int grp  = lane >> 2;
    const int tg   = lane & 3;

    float acc[4][4][4];
    #pragma unroll
    for (int i = 0; i < 4; i++)
        #pragma unroll
        for (int j = 0; j < 4; j++)
            #pragma unroll
            for (int c = 0; c < 4; c++) acc[i][j][c] = 0.0f;

    int s = 0;
    for (int it = 0; it < iters; ++it) {
        CP_WAIT(1);
        __syncthreads();

        if (it + 2 < iters) {
            int s2 = s + 2; if (s2 >= NSTAGE) s2 -= NSTAGE;
            issue(usm + (uint32_t)s2 * STG_BYTES, kb + (it + 2) * GBK);
        }
        CP_COMMIT();

        const char* stg = smraw + (uint32_t)s * STG_BYTES;
        const char* sA  = stg + A_OFF;
        const char* sB  = stg + B_OFF;

        #pragma unroll
        for (int ks = 0; ks < 4; ks++) {
            const int c0 = ks * 2;
            const int c1 = ks * 2 + 1;
            const int cA = ks * 2 + (tg >> 1);
            const uint32_t aoff = (uint32_t)((tg & 1) * 8);

            uint32_t bfr[4][2];
            #pragma unroll
            for (int ni = 0; ni < 4; ni++) {
                int br = wn + ni * 8 + grp;
                const char* rowp = sB + br * 128 + tg * 4;
                float v0 = *(const float*)(rowp + ((c0 ^ (br & 7)) * 16));
                float v1 = *(const float*)(rowp + ((c1 ^ (br & 7)) * 16));
                bfr[ni][0] = f2tf32(v0);
                bfr[ni][1] = f2tf32(v1);
            }
            #pragma unroll
            for (int mi = 0; mi < 4; mi++) {
                int ar0 = wm + mi * 16 + grp;
                int ar1 = ar0 + 8;
                uint2 v0 = *(const uint2*)(sA + ar0 * 128 +
                             ((cA ^ (ar0 & 7)) * 16) + aoff);
                uint2 v1 = *(const uint2*)(sA + ar1 * 128 +
                             ((cA ^ (ar1 & 7)) * 16) + aoff);
                uint32_t a[4] = { v0.x, v1.x, v0.y, v1.y };
                #pragma unroll
                for (int ni = 0; ni < 4; ni++)
                    mma_tf32(acc[mi][ni], a, bfr[ni][0], bfr[ni][1]);
            }
        }
        s = (s == NSTAGE - 1) ? 0 : s + 1;
    }

    // ---- epilogue ----
    float* Cb = (EPI == 2 || EPI == 4) ? (C + (size_t)blockIdx.z * partStride) : C;
    const int erow = lane >> 2;
    const int ecol = (lane & 3) * 2;
    #pragma unroll
    for (int mi = 0; mi < 4; mi++) {
        #pragma unroll
        for (int ni = 0; ni < 4; ni++) {
            int r0 = m0 + wm + mi * 16 + erow;
            int c0 = n0 + wn + ni * 8 + ecol;
            if (c0 >= nlim) continue;
            float* p0 = Cb + (size_t)r0 * ldc + c0;
            float* p1 = Cb + (size_t)(r0 + 8) * ldc + c0;
            if (EPI == 3) {
                float b0 = bias[c0], b1 = bias[c0 + 1];
                float v[4] = { acc[mi][ni][0] + b0, acc[mi][ni][1] + b1,
                               acc[mi][ni][2] + b0, acc[mi][ni][3] + b1 };
                #pragma unroll
                for (int q = 0; q < 4; q++)
                    v[q] = fmaxf(v[q], 0.0f) + log1pf(__expf(-fabsf(v[q])));
                *(float2*)p0 = make_float2(v[0], v[1]);
                *(float2*)p1 = make_float2(v[2], v[3]);
            } else {
                *(float2*)p0 = make_float2(acc[mi][ni][0], acc[mi][ni][1]);
                *(float2*)p1 = make_float2(acc[mi][ni][2], acc[mi][ni][3]);
            }
        }
    }

    if (EPI == 4) {
        // last-CTA-per-tile reduces the SPLITK partials into Cfinal
        __shared__ int lastFlag;
        __threadfence();
        __syncthreads();
        const int tidx = blockIdx.y * gridDim.x + blockIdx.x;
        if (tid == 0)
            lastFlag = (atomicAdd(&cnt[tidx], 1) == SPLITK - 1);
        __syncthreads();
        if (lastFlag) {
            const int n4 = GBN / 4;   // 32 float4 per row
            for (int e = tid; e < GBM * n4; e += 256) {
                int rr = e / n4;
                int cc = e - rr * n4;
                size_t off = (size_t)(m0 + rr) * ldc + n0 + cc * 4;
                float4 a = *(const float4*)(C + off);
                #pragma unroll
                for (int s2 = 1; s2 < SPLITK; s2++) {
                    float4 b = *(const float4*)(C + (size_t)s2 * partStride + off);
                    a.x += b.x; a.y += b.y; a.z += b.z; a.w += b.w;
                }
                *(float4*)(Cfinal + off) = a;
            }
            if (tid == 0) cnt[tidx] = 0;   // reset for next graph replay
        }
    }
}

// ---------------- reduces ----------------
// GEMM3 partials -> x_db (plain) + dt_in (tf32, permuted, first 128 cols)
__global__ void reduce3_kernel() {
    int i = blockIdx.x * blockDim.x + threadIdx.x;
    const int n = BB * XPN;
    if (i >= n) return;
    float s = 0.0f;
    #pragma unroll 4
    for (int s2 = 0; s2 < SPLIT3; s2++) s += g_part3[(size_t)s2 * n + i];
    g_xdb[i] = s;
    int r = i / XPN, c = i - r * XPN;
    if (c < DTRANK)
        g_dtin[r * DTRANK + (c & ~7) + kperm(c & 7)] = __uint_as_float(f2tf32(s));
}

// ---------------- small helpers ----------------
__global__ void precompute_A_kernel(const float* __restrict__ A_log) {
    int i = blockIdx.x * blockDim.x + threadIdx.x;
    if (i < DINNER * DSTATE) g_A[i] = -expf(A_log[i]);
}

// round fp32 -> tf32 AND k-permute per 8-group (one 8-group per thread)
__global__ void round_perm_kernel(const float4* __restrict__ in,
                                  uint4* __restrict__ out, int n8) {
    int i = blockIdx.x * blockDim.x + threadIdx.x;
    if (i >= n8) return;
    float4 lo = in[2 * i];
    float4 hi = in[2 * i + 1];
    uint4 o0, o1;
    o0.x = f2tf32(lo.x); o0.y = f2tf32(hi.x);
    o0.z = f2tf32(lo.y); o0.w = f2tf32(hi.y);
    o1.x = f2tf32(lo.z); o1.y = f2tf32(hi.z);
    o1.z = f2tf32(lo.w); o1.w = f2tf32(hi.w);
    out[2 * i]     = o0;
    out[2 * i + 1] = o1;
}

// ---------------- conv window shift + SiLU (xc stored tf32+permuted) --------
__global__ void conv_kernel(const float* __restrict__ cs_in,
                            const float* __restrict__ conv_w,
                            const float* __restrict__ conv_b,
                            float* __restrict__ cs_out)
{
    int idx = blockIdx.x * blockDim.x + threadIdx.x;
    int b = idx >> 13;
    int d = idx & (DINNER - 1);
    float4 cs = ((const float4*)cs_in)[idx];
    float4 w  = ((const float4*)conv_w)[d];
    float xi  = g_xz[(size_t)b * (2*DINNER) + d];
    float s = cs.y*w.x + cs.z*w.y + cs.w*w.z + xi*w.w + conv_b[d];
    float sig = 1.0f / (1.0f + __expf(-s));
    float xc = s * sig;
    g_xc[(idx & ~7) + kperm(d & 7)] = __uint_as_float(f2tf32(xc));
    ((float4*)cs_out)[idx] = make_float4(cs.y, cs.z, cs.w, xi);
}

// ---------------- SSM state update + y (y stored tf32+permuted) -------------
__global__ void ssm_kernel(const float* __restrict__ ssm_in,
                           const float* __restrict__ D_param,
                           float* __restrict__ ssm_out)
{
    __shared__ float bm[DSTATE], cm[DSTATE];
    const int b = blockIdx.y;
    const int d = blockIdx.x * blockDim.x + threadIdx.x;
    if (threadIdx.x < 2*DSTATE) {
        float v = g_xdb[b * XPN + DTRANK + threadIdx.x];
        if (threadIdx.x < DSTATE) bm[threadIdx.x] = v;
        else                      cm[threadIdx.x - DSTATE] = v;
    }
    __syncthreads();

    const int bd = b * DINNER + d;
    const int pp = (bd & ~7) + kperm(d & 7);
    const float dtv = g_dt[bd];
    const float xcv = g_xc[pp];
    const float xdt = xcv * dtv;
    const size_t base = (size_t)bd * DSTATE;

    float yacc = 0.0f;
    #pragma unroll
    for (int n = 0; n < DSTATE; n += 4) {
        float4 a  = *(const float4*)&g_A[d * DSTATE + n];
        float4 st = *(const float4*)&ssm_in[base + n];
        float4 ns;
        ns.x = st.x * __expf(a.x * dtv) + xdt * bm[n+0];
        ns.y = st.y * __expf(a.y * dtv) + xdt * bm[n+1];
        ns.z = st.z * __expf(a.z * dtv) + xdt * bm[n+2];
        ns.w = st.w * __expf(a.w * dtv) + xdt * bm[n+3];
        yacc += ns.x * cm[n+0] + ns.y * cm[n+1] + ns.z * cm[n+2] + ns.w * cm[n+3];
        *(float4*)&ssm_out[base + n] = ns;
    }
    yacc += D_param[d] * xcv;
    float zv = g_xz[(size_t)b * (2*DINNER) + DINNER + d];
    yacc *= zv / (1.0f + __expf(-zv));

    g_y[pp] = __uint_as_float(f2tf32(yacc));
}

// ---------------- launch ----------------
extern "C" void kernel_launch(void* const* d_in, const int* in_sizes, int n_in,
                              void* d_out, int out_size)
{
    const float* x       = (const float*)d_in[0];
    const float* cs_in   = (const float*)d_in[1];
    const float* ssm_in  = (const float*)d_in[2];
    const float* W_in    = (const float*)d_in[3];
    const float* conv_w  = (const float*)d_in[4];
    const float* conv_b  = (const float*)d_in[5];
    const float* W_xproj = (const float*)d_in[6];
    const float* W_dt    = (const float*)d_in[7];
    const float* b_dt    = (const float*)d_in[8];
    const float* A_log   = (const float*)d_in[9];
    const float* D_param = (const float*)d_in[10];
    const float* W_out   = (const float*)d_in[11];

    float* out     = (float*)d_out;
    float* cs_out  = out + (size_t)BB * DMODEL;
    float* ssm_out = cs_out + (size_t)BB * DINNER * 4;

    void *p_xz, *p_xc, *p_dtin, *p_dt, *p_xt, *p_y, *p_part, *p_part3, *p_cnt;
    cudaGetSymbolAddress(&p_xz,   g_xz);
    cudaGetSymbolAddress(&p_xc,   g_xc);
    cudaGetSymbolAddress(&p_dtin, g_dtin);
    cudaGetSymbolAddress(&p_dt,   g_dt);
    cudaGetSymbolAddress(&p_xt,   g_xt);
    cudaGetSymbolAddress(&p_y,    g_y);
    cudaGetSymbolAddress(&p_part, g_part);
    cudaGetSymbolAddress(&p_part3, g_part3);
    cudaGetSymbolAddress(&p_cnt,  g_cnt6);

    const int HSM = NSTAGE * STG_BYTES;   // 98304 bytes -> 2 CTAs/SM
    cudaFuncSetAttribute(tf32_gemm<0,1>,      cudaFuncAttributeMaxDynamicSharedMemorySize, HSM);
    cudaFuncSetAttribute(tf32_gemm<2,SPLIT3>, cudaFuncAttributeMaxDynamicSharedMemorySize, HSM);
    cudaFuncSetAttribute(tf32_gemm<3,1>,      cudaFuncAttributeMaxDynamicSharedMemorySize, HSM);
    cudaFuncSetAttribute(tf32_gemm<4,SPLIT6>, cudaFuncAttributeMaxDynamicSharedMemorySize, HSM);

    // 0: A precompute  1,2: x round+permute halves  3: GEMM1 (profiled)
    precompute_A_kernel<<<(DINNER*DSTATE + 255)/256, 256>>>(A_log);
    {
        const int n8 = BB * DMODEL / 8;         // 65536 groups
        const int half = n8 / 2;
        round_perm_kernel<<<(half + 255)/256, 256>>>(
            (const float4*)x, (uint4*)p_xt, half);
        round_perm_kernel<<<(half + 255)/256, 256>>>(
            (const float4*)(x + (size_t)half * 8),
            (uint4*)((float*)p_xt + (size_t)half * 8), half);
    }

    // GEMM1: xz[256,16384] = x @ W_in^T
    tf32_gemm<0,1><<<dim3((2*DINNER)/GBN, BB/GBM, 1), 256, HSM>>>(
        (const float*)p_xt, DMODEL, W_in, DMODEL,
        (float*)p_xz, 2*DINNER, DMODEL, 2*DINNER, 0, nullptr, nullptr, nullptr);

    // conv + SiLU (writes cs_out + xc tf32/permuted)
    conv_kernel<<<(BB*DINNER)/256, 256>>>(cs_in, conv_w, conv_b, cs_out);

    // GEMM3: x_db partials = xc @ W_xproj^T  (N=160 clamped, split-K=32)
    tf32_gemm<2,SPLIT3><<<dim3(2, BB/GBM, SPLIT3), 256, HSM>>>(
        (const float*)p_xc, DINNER, W_xproj, DINNER,
        (float*)p_part3, XPN, DINNER, XPN, (size_t)BB * XPN, nullptr,
        nullptr, nullptr);
    reduce3_kernel<<<(BB*XPN + 255)/256, 256>>>();

    // GEMM4: dt = softplus(dt_in @ W_dt^T + b_dt)   (K=128)
    tf32_gemm<3,1><<<dim3(DINNER/GBN, BB/GBM, 1), 256, HSM>>>(
        (const float*)p_dtin, DTRANK, W_dt, DTRANK,
        (float*)p_dt, DINNER, DTRANK, DINNER, 0, b_dt, nullptr, nullptr);

    // SSM update + y (emits y tf32/permuted)
    ssm_kernel<<<dim3(DINNER/256, BB), 256>>>(ssm_in, D_param, ssm_out);

    // GEMM6: partials + fused last-CTA reduction into out
    tf32_gemm<4,SPLIT6><<<dim3(DMODEL/GBN, BB/GBM, SPLIT6), 256, HSM>>>(
        (const float*)p_y, DINNER, W_out, DINNER,
        (float*)p_part, DMODEL, DINNER, DMODEL, (size_t)BB * DMODEL, nullptr,
        out, (int*)p_cnt);
}